// round 14
// baseline (speedup 1.0000x reference)
#include <cuda_runtime.h>

#define NND 100000
#define NE  1000000

// ---------------- device scratch (static, allocation-free) ----------------
__device__ float g_mean1[(size_t)NND * 64];  // layer-1 neighbor mean of x
__device__ float g_h   [(size_t)NND * 128];  // hidden activations
__device__ float g_p   [(size_t)NND * 64];   // h @ W2l (pre-aggregation)
__device__ int   g_cnt [NND];                // in-degree
__device__ int   g_px  [NND];                // block-local exclusive scan
__device__ int   g_bsum [512];               // per-block sums
__device__ int   g_bsumx[512];               // scanned block sums
__device__ int   g_rowptr[NND + 1];          // CSR row pointers
__device__ int   g_cur [NND];                // fill cursors
__device__ int   g_nbr [NE];                 // CSR neighbor (src) lists

// ---------------- f32x2 helpers (sm_103a packed fp32 SIMD) ----------------
__device__ __forceinline__ unsigned long long pk2(float lo, float hi) {
    unsigned long long r;
    asm("mov.b64 %0, {%1, %2};" : "=l"(r) : "f"(lo), "f"(hi));
    return r;
}
__device__ __forceinline__ void upk2(float& lo, float& hi, unsigned long long v) {
    asm("mov.b64 {%0, %1}, %2;" : "=f"(lo), "=f"(hi) : "l"(v));
}
#define FMA2(d, a, b) \
    asm("fma.rn.f32x2 %0, %1, %2, %0;" : "+l"(d) : "l"(a), "l"(b))

__device__ __forceinline__ int clampn(int v) {
    return (v < 0) ? 0 : (v >= NND ? NND - 1 : v);
}

// ---------------- CSR build ----------------
__global__ void k_zero() {
    int i = blockIdx.x * 256 + threadIdx.x;
    if (i < NND) g_cnt[i] = 0;
}

__global__ void k_edges(const int* __restrict__ ei) {
    int e = blockIdx.x * 256 + threadIdx.x;
    if (e < NE) atomicAdd(&g_cnt[clampn(ei[NE + e])], 1);
}

// shuffle-based block scan (256 threads) of g_cnt + per-block totals
__global__ void k_scanA() {
    __shared__ int ws[8];
    int tid = threadIdx.x;
    int i = blockIdx.x * 256 + tid;
    int lane = tid & 31, w = tid >> 5;
    int v = (i < NND) ? g_cnt[i] : 0;
    int s = v;
    #pragma unroll
    for (int o = 1; o < 32; o <<= 1) {
        int t = __shfl_up_sync(0xffffffffu, s, o);
        if (lane >= o) s += t;
    }
    if (lane == 31) ws[w] = s;
    __syncthreads();
    if (w == 0) {
        int t = (lane < 8) ? ws[lane] : 0;
        #pragma unroll
        for (int o = 1; o < 8; o <<= 1) {
            int u = __shfl_up_sync(0xffffffffu, t, o);
            if (lane >= o) t += u;
        }
        if (lane < 8) ws[lane] = t;
    }
    __syncthreads();
    int incl = s + ((w > 0) ? ws[w - 1] : 0);
    if (i < NND) g_px[i] = incl - v;         // exclusive
    if (tid == 255) g_bsum[blockIdx.x] = incl;
}

// scan the block sums (single block of 512, shuffle-based)
__global__ void k_scanB(int nb) {
    __shared__ int ws[16];
    int tid = threadIdx.x;
    int lane = tid & 31, w = tid >> 5;
    int v = (tid < nb) ? g_bsum[tid] : 0;
    int s = v;
    #pragma unroll
    for (int o = 1; o < 32; o <<= 1) {
        int t = __shfl_up_sync(0xffffffffu, s, o);
        if (lane >= o) s += t;
    }
    if (lane == 31) ws[w] = s;
    __syncthreads();
    if (w == 0) {
        int t = (lane < 16) ? ws[lane] : 0;
        #pragma unroll
        for (int o = 1; o < 16; o <<= 1) {
            int u = __shfl_up_sync(0xffffffffu, t, o);
            if (lane >= o) t += u;
        }
        if (lane < 16) ws[lane] = t;
    }
    __syncthreads();
    int incl = s + ((w > 0) ? ws[w - 1] : 0);
    if (tid < nb) g_bsumx[tid] = incl - v;   // exclusive
}

__global__ void k_scanC() {
    int i = blockIdx.x * 256 + threadIdx.x;
    if (i < NND) {
        int r = g_px[i] + g_bsumx[i >> 8];
        g_rowptr[i] = r;
        g_cur[i] = r;
    }
    if (i == 0) g_rowptr[NND] = NE;
}

__global__ void k_fill(const int* __restrict__ ei) {
    int e = blockIdx.x * 256 + threadIdx.x;
    if (e < NE) {
        int d = clampn(ei[NE + e]);
        int pos = atomicAdd(&g_cur[d], 1);
        g_nbr[pos] = clampn(ei[e]);
    }
}

// ---------------- gather1: mean1[node] = mean of x over neighbors ----------------
__global__ void k_gather1(const float* __restrict__ xin) {
    int t = blockIdx.x * 256 + threadIdx.x;      // exactly NND*16 threads
    int node = t >> 4;
    int c = t & 15;
    int s0 = __ldg(&g_rowptr[node]);
    int s1 = __ldg(&g_rowptr[node + 1]);
    float4 a0 = make_float4(0.f, 0.f, 0.f, 0.f);
    float4 a1 = a0, a2 = a0, a3 = a0;
    int j = s0;
    for (; j + 4 <= s1; j += 4) {
        int sA = __ldg(&g_nbr[j]);
        int sB = __ldg(&g_nbr[j + 1]);
        int sC = __ldg(&g_nbr[j + 2]);
        int sD = __ldg(&g_nbr[j + 3]);
        float4 vA = __ldg((const float4*)xin + (size_t)sA * 16 + c);
        float4 vB = __ldg((const float4*)xin + (size_t)sB * 16 + c);
        float4 vC = __ldg((const float4*)xin + (size_t)sC * 16 + c);
        float4 vD = __ldg((const float4*)xin + (size_t)sD * 16 + c);
        a0.x += vA.x; a0.y += vA.y; a0.z += vA.z; a0.w += vA.w;
        a1.x += vB.x; a1.y += vB.y; a1.z += vB.z; a1.w += vB.w;
        a2.x += vC.x; a2.y += vC.y; a2.z += vC.z; a2.w += vC.w;
        a3.x += vD.x; a3.y += vD.y; a3.z += vD.z; a3.w += vD.w;
    }
    for (; j < s1; j++) {
        int sA = __ldg(&g_nbr[j]);
        float4 vA = __ldg((const float4*)xin + (size_t)sA * 16 + c);
        a0.x += vA.x; a0.y += vA.y; a0.z += vA.z; a0.w += vA.w;
    }
    int deg = s1 - s0;
    float ri = 1.f / (float)(deg < 1 ? 1 : deg);
    float4 acc = make_float4((a0.x + a1.x + a2.x + a3.x) * ri,
                             (a0.y + a1.y + a2.y + a3.y) * ri,
                             (a0.z + a1.z + a2.z + a3.z) * ri,
                             (a0.w + a1.w + a2.w + a3.w) * ri);
    ((float4*)g_mean1)[t] = acc;
}

// ---------------- gather2 fused with finalize: out += mean of p over neighbors ----------------
__global__ void k_gather2(float* __restrict__ out) {
    int t = blockIdx.x * 256 + threadIdx.x;      // exactly NND*16 threads
    int node = t >> 4;
    int c = t & 15;
    int s0 = __ldg(&g_rowptr[node]);
    int s1 = __ldg(&g_rowptr[node + 1]);
    float4 a0 = make_float4(0.f, 0.f, 0.f, 0.f);
    float4 a1 = a0, a2 = a0, a3 = a0;
    int j = s0;
    for (; j + 4 <= s1; j += 4) {
        int sA = __ldg(&g_nbr[j]);
        int sB = __ldg(&g_nbr[j + 1]);
        int sC = __ldg(&g_nbr[j + 2]);
        int sD = __ldg(&g_nbr[j + 3]);
        float4 vA = __ldg((const float4*)g_p + (size_t)sA * 16 + c);
        float4 vB = __ldg((const float4*)g_p + (size_t)sB * 16 + c);
        float4 vC = __ldg((const float4*)g_p + (size_t)sC * 16 + c);
        float4 vD = __ldg((const float4*)g_p + (size_t)sD * 16 + c);
        a0.x += vA.x; a0.y += vA.y; a0.z += vA.z; a0.w += vA.w;
        a1.x += vB.x; a1.y += vB.y; a1.z += vB.z; a1.w += vB.w;
        a2.x += vC.x; a2.y += vC.y; a2.z += vC.z; a2.w += vC.w;
        a3.x += vD.x; a3.y += vD.y; a3.z += vD.z; a3.w += vD.w;
    }
    for (; j < s1; j++) {
        int sA = __ldg(&g_nbr[j]);
        float4 vA = __ldg((const float4*)g_p + (size_t)sA * 16 + c);
        a0.x += vA.x; a0.y += vA.y; a0.z += vA.z; a0.w += vA.w;
    }
    int deg = s1 - s0;
    float ri = 1.f / (float)(deg < 1 ? 1 : deg);
    float4 o = ((const float4*)out)[t];
    o.x = fmaf(a0.x + a1.x + a2.x + a3.x, ri, o.x);
    o.y = fmaf(a0.y + a1.y + a2.y + a3.y, ri, o.y);
    o.z = fmaf(a0.z + a1.z + a2.z + a3.z, ri, o.z);
    o.w = fmaf(a0.w + a1.w + a2.w + a3.w, ri, o.w);
    ((float4*)out)[t] = o;
}

// ---------------- GEMM: tile 128 nodes x 64 cols (blockIdx.y = col half) ----------------
// MODE 1: h[:, half] = relu( concat(mean1, x) @ [W1l;W1r][:, half] + b1[half] )
// MODE 2: half 0 -> g_p = h @ W2l ; half 1 -> out = h @ W2r + b2
// W staged in smem (32KB only). A read DIRECTLY from global via __ldg:
// each (node,k4) float4 is touched by exactly one warp (8 lanes dedup to 1 req),
// so A traffic = tile bytes with zero staging instrs and one barrier total.
// 256 threads: cg = tid&7 (cols cg*4..+3 and 32+cg*4..+3), ng = tid>>3 (nodes ng*4..+3).
extern __shared__ float sm[];

template <int MODE>
__global__ __launch_bounds__(256, 3)
void k_gemm(const float* __restrict__ xin, const float* __restrict__ Wa,
            const float* __restrict__ Wb, const float* __restrict__ bias,
            float* __restrict__ outr) {
    float* Ws = sm;                          // 128 k x 64 c floats
    int tid = threadIdx.x;
    int nodeB = blockIdx.x * 128;
    int h = blockIdx.y;                      // column half

    // ---- stage W (2048 float4 = 32KB) ----
    #pragma unroll
    for (int m = 0; m < 8; m++) {
        int j = tid + 256 * m;
        int k = j >> 4, c4 = j & 15;
        float4 v;
        if (MODE == 1) {        // stacked rows 0-63 W1l, 64-127 W1r; cols h*64..
            v = __ldg((const float4*)(k < 64 ? Wa : Wb) + (k & 63) * 32 + h * 16 + c4);
        } else {                // half 0 = W2l, half 1 = W2r, each [128][64]
            v = __ldg((const float4*)(h ? Wb : Wa) + j);
        }
        ((float4*)Ws)[j] = v;
    }
    __syncthreads();

    int cg = tid & 7;           // cols: cg*4..+3 and 32+cg*4..+3 (of this 64 half)
    int ng = tid >> 3;          // nodes ng*4..+3
    int cL = cg * 4;
    int cR = 32 + cg * 4;
    int n0 = ng * 4;

    // clamped node indices (reads valid; writes guarded)
    int nd[4];
    #pragma unroll
    for (int j = 0; j < 4; j++) {
        int g = nodeB + n0 + j;
        nd[j] = (g >= NND) ? NND - 1 : g;
    }

    // ---- bias / acc init ----
    float bl[4], br[4];
    #pragma unroll
    for (int q = 0; q < 4; q++) {
        if (MODE == 1) {
            bl[q] = __ldg(bias + h * 64 + cL + q);
            br[q] = __ldg(bias + h * 64 + cR + q);
        } else if (h == 1) {
            bl[q] = __ldg(bias + cL + q);
            br[q] = __ldg(bias + cR + q);
        } else { bl[q] = 0.f; br[q] = 0.f; }
    }
    unsigned long long acc[4][4];
    #pragma unroll
    for (int j = 0; j < 4; j++) {
        acc[j][0] = pk2(bl[0], bl[1]);
        acc[j][1] = pk2(bl[2], bl[3]);
        acc[j][2] = pk2(br[0], br[1]);
        acc[j][3] = pk2(br[2], br[3]);
    }

    // ---- two K-phases of 64 (16 k4-groups each) ----
    #pragma unroll
    for (int ph = 0; ph < 2; ph++) {
        // per-node A row pointers for this phase
        const float4* ap[4];
        #pragma unroll
        for (int j = 0; j < 4; j++) {
            if (MODE == 1)
                ap[j] = ph ? ((const float4*)xin + (size_t)nd[j] * 16)
                           : ((const float4*)g_mean1 + (size_t)nd[j] * 16);
            else
                ap[j] = (const float4*)g_h + (size_t)nd[j] * 32 + ph * 16;
        }
        #pragma unroll 4
        for (int t = 0; t < 16; t++) {
            float4 av[4];
            #pragma unroll
            for (int j = 0; j < 4; j++) av[j] = __ldg(ap[j] + t);
            #pragma unroll
            for (int kk = 0; kk < 4; kk++) {
                int k = ph * 64 + t * 4 + kk;
                ulonglong2 wA = *(const ulonglong2*)(Ws + k * 64 + cL);
                ulonglong2 wB = *(const ulonglong2*)(Ws + k * 64 + cR);
                #pragma unroll
                for (int j = 0; j < 4; j++) {
                    float a = (kk == 0) ? av[j].x : (kk == 1) ? av[j].y
                            : (kk == 2) ? av[j].z : av[j].w;
                    unsigned long long aa = pk2(a, a);
                    FMA2(acc[j][0], aa, wA.x);
                    FMA2(acc[j][1], aa, wA.y);
                    FMA2(acc[j][2], aa, wB.x);
                    FMA2(acc[j][3], aa, wB.y);
                }
            }
        }
    }

    // ---- write out ----
    #pragma unroll
    for (int j = 0; j < 4; j++) {
        int node = nodeB + n0 + j;
        if (node < NND) {
            float l0,l1,l2,l3,r0,r1,r2,r3;
            upk2(l0, l1, acc[j][0]);
            upk2(l2, l3, acc[j][1]);
            upk2(r0, r1, acc[j][2]);
            upk2(r2, r3, acc[j][3]);
            if (MODE == 1) {
                float* dp = g_h + (size_t)node * 128 + h * 64;
                *(float4*)(dp + cL) = make_float4(fmaxf(l0,0.f), fmaxf(l1,0.f),
                                                  fmaxf(l2,0.f), fmaxf(l3,0.f));
                *(float4*)(dp + cR) = make_float4(fmaxf(r0,0.f), fmaxf(r1,0.f),
                                                  fmaxf(r2,0.f), fmaxf(r3,0.f));
            } else {
                float* dst = (h ? outr : g_p) + (size_t)node * 64;
                *(float4*)(dst + cL) = make_float4(l0, l1, l2, l3);
                *(float4*)(dst + cR) = make_float4(r0, r1, r2, r3);
            }
        }
    }
}

// ---------------- launch ----------------
extern "C" void kernel_launch(void* const* d_in, const int* in_sizes, int n_in,
                              void* d_out, int out_size) {
    const float* x   = nullptr;
    const float* b1  = nullptr;
    const float* b2  = nullptr;
    const int*   ei  = nullptr;
    const float* W[4] = {nullptr, nullptr, nullptr, nullptr};
    int wn = 0;
    for (int i = 0; i < n_in; i++) {
        int sz = in_sizes[i];
        if      (sz == NND * 64)  x  = (const float*)d_in[i];
        else if (sz == 2 * NE)    ei = (const int*)d_in[i];
        else if (sz == 128)       b1 = (const float*)d_in[i];
        else if (sz == 64)        b2 = (const float*)d_in[i];
        else if (sz == 8192 && wn < 4) W[wn++] = (const float*)d_in[i];
    }
    const float* W1l = W[0];
    const float* W1r = W[1];
    const float* W2l = W[2];
    const float* W2r = W[3];
    float* out = (float*)d_out;

    const int SMG = 32768;                       // W only
    cudaFuncSetAttribute(k_gemm<1>, cudaFuncAttributeMaxDynamicSharedMemorySize, SMG);
    cudaFuncSetAttribute(k_gemm<2>, cudaFuncAttributeMaxDynamicSharedMemorySize, SMG);

    const int NB = (NND + 255) / 256;            // 391
    dim3 gemm_grid((NND + 127) / 128, 2);        // 782 x 2

    // CSR build
    k_zero <<<NB, 256>>>();
    k_edges<<<(NE + 255) / 256, 256>>>(ei);
    k_scanA<<<NB, 256>>>();
    k_scanB<<<1, 512>>>(NB);
    k_scanC<<<NB, 256>>>();
    k_fill <<<(NE + 255) / 256, 256>>>(ei);
    // layer 1
    k_gather1<<<6250, 256>>>(x);                 // mean of x -> g_mean1
    k_gemm<1><<<gemm_grid, 256, SMG>>>(x, W1l, W1r, b1, nullptr);
    // layer 2 (GEMM commuted before aggregation; gather fused with +=)
    k_gemm<2><<<gemm_grid, 256, SMG>>>(nullptr, W2l, W2r, b2, out);
    k_gather2<<<6250, 256>>>(out);               // out += mean of p
}